// round 3
// baseline (speedup 1.0000x reference)
#include <cuda_runtime.h>

typedef unsigned long long u64;

#define CB  2048
#define CT  512
#define CI  64
#define CH  32
#define CG  128

// Scratch for input projections, gate-paired per batch:
// g_xg[t*131072 + b*64 + pg*32 + j] = {xg[b][(2pg)*32+j], xg[b][(2pg+1)*32+j]}
// One extra timestep so K2's prefetch of t+1 never reads OOB.
__device__ u64 g_xg[(size_t)(CT + 1) * CB * 64];

__device__ __forceinline__ u64 ffma2(u64 a, u64 b, u64 c) {
    u64 d;
    asm("fma.rn.f32x2 %0, %1, %2, %3;" : "=l"(d) : "l"(a), "l"(b), "l"(c));
    return d;
}
__device__ __forceinline__ u64 pack2(float lo, float hi) {
    u64 d;
    asm("mov.b64 %0, {%1, %2};" : "=l"(d) : "f"(lo), "f"(hi));
    return d;
}
__device__ __forceinline__ float2 unpack2(u64 v) {
    float2 r;
    asm("mov.b64 {%0, %1}, %2;" : "=f"(r.x), "=f"(r.y) : "l"(v));
    return r;
}

// ---------------------------------------------------------------------------
// K1: input projection GEMM.  xg[t][b][g] = sum_k x[b][t][k] * W_ih[g][k] + bias
// Block: 256 threads, tile = 128 batch rows x 128 gates, K=64.
// Thread: 2 j-columns (jj0, jj0+1) x 4 gate-blocks x 8 batch rows (f32x2 over
// batch pairs). Weights staged in smem as duplicated u64 -> no packs in loop.
// ---------------------------------------------------------------------------
#define WTS2 130   // u64 stride for Wt2 rows (gates)
#define XTS  132   // float stride for xs rows (batch)

extern __shared__ char sm1[];

__global__ __launch_bounds__(256, 2) void k1_inproj(
    const float* __restrict__ x, const float* __restrict__ Wih,
    const float* __restrict__ bih, const float* __restrict__ bhh)
{
    u64*   Wt2 = (u64*)sm1;                       // Wt2[k*WTS2 + g] = {w,w}
    float* xs  = (float*)(sm1 + 64 * WTS2 * 8);   // xs[k*XTS + r]
    const int tid = threadIdx.x;
    const int t   = blockIdx.y;
    const int bt  = blockIdx.x * 128;

    // Stage W_ih duplicated: Wt2[k][g] = {W[g][k], W[g][k]}
    #pragma unroll
    for (int idx = tid; idx < CG * CI; idx += 256) {
        int g = idx >> 6, k = idx & 63;
        float w = Wih[idx];
        Wt2[k * WTS2 + g] = pack2(w, w);
    }
    // Stage x tile transposed: xs[k][r]
    #pragma unroll
    for (int idx = tid; idx < 128 * CI; idx += 256) {
        int r = idx >> 6, k = idx & 63;
        xs[k * XTS + r] = x[((size_t)(bt + r) * CT + t) * CI + k];
    }
    __syncthreads();

    const int tx = tid & 15, ty = tid >> 4;
    const int jj0 = tx * 2, r0 = ty * 8;

    // acc[q][gb][p] : q = jj0+q, gate = gb*32+jj0+q, halves = batch pair p
    u64 acc[2][4][4];
    #pragma unroll
    for (int q = 0; q < 2; q++)
        #pragma unroll
        for (int gb = 0; gb < 4; gb++) {
            int g = gb * 32 + jj0 + q;
            float bs = bih[g] + bhh[g];
            u64 bd = pack2(bs, bs);
            #pragma unroll
            for (int p = 0; p < 4; p++) acc[q][gb][p] = bd;
        }

    #pragma unroll 4
    for (int k = 0; k < CI; k++) {
        const ulonglong2 xa = *(const ulonglong2*)&xs[k * XTS + r0];
        const ulonglong2 xb = *(const ulonglong2*)&xs[k * XTS + r0 + 4];
        u64 xp[4] = {xa.x, xa.y, xb.x, xb.y};
        const ulonglong2 w0 = *(const ulonglong2*)&Wt2[k * WTS2 +  0 + jj0];
        const ulonglong2 w1 = *(const ulonglong2*)&Wt2[k * WTS2 + 32 + jj0];
        const ulonglong2 w2 = *(const ulonglong2*)&Wt2[k * WTS2 + 64 + jj0];
        const ulonglong2 w3 = *(const ulonglong2*)&Wt2[k * WTS2 + 96 + jj0];
        #pragma unroll
        for (int p = 0; p < 4; p++) {
            acc[0][0][p] = ffma2(xp[p], w0.x, acc[0][0][p]);
            acc[0][1][p] = ffma2(xp[p], w1.x, acc[0][1][p]);
            acc[0][2][p] = ffma2(xp[p], w2.x, acc[0][2][p]);
            acc[0][3][p] = ffma2(xp[p], w3.x, acc[0][3][p]);
            acc[1][0][p] = ffma2(xp[p], w0.y, acc[1][0][p]);
            acc[1][1][p] = ffma2(xp[p], w1.y, acc[1][1][p]);
            acc[1][2][p] = ffma2(xp[p], w2.y, acc[1][2][p]);
            acc[1][3][p] = ffma2(xp[p], w3.y, acc[1][3][p]);
        }
    }

    // Store gate-paired per batch: [t][b][pg][j] = {gate 2pg*32+j, gate (2pg+1)*32+j}
    #pragma unroll
    for (int p = 0; p < 4; p++) {
        size_t be = (size_t)(bt + r0 + 2 * p);
        u64* de = g_xg + (size_t)t * (CB * 64) + be * 64;
        u64* dо = de + 64;
        #pragma unroll
        for (int pg = 0; pg < 2; pg++) {
            float2 a0 = unpack2(acc[0][2 * pg][p]);       // gate 2pg*32+jj0
            float2 b0 = unpack2(acc[0][2 * pg + 1][p]);   // gate (2pg+1)*32+jj0
            float2 a1 = unpack2(acc[1][2 * pg][p]);       // jj0+1
            float2 b1 = unpack2(acc[1][2 * pg + 1][p]);
            ulonglong2 ve, vo;
            ve.x = pack2(a0.x, b0.x);  ve.y = pack2(a1.x, b1.x);
            vo.x = pack2(a0.y, b0.y);  vo.y = pack2(a1.y, b1.y);
            *(ulonglong2*)(de + pg * 32 + jj0) = ve;
            *(ulonglong2*)(dо + pg * 32 + jj0) = vo;
        }
    }
}

// ---------------------------------------------------------------------------
// K2: recurrence. One warp per 4 batch elements, lane j = hidden unit j.
// W_hh register-resident as gate-pairs: wr0[k]={W[i_j][k],W[f_j][k]},
// wr1[k]={W[g_j][k],W[o_j][k]}. h exchanged via smem, pre-duplicated u64.
// Inner loop per k: 2 broadcast LDS.128 + 8 FFMA2. fc fused at the end.
// ---------------------------------------------------------------------------
__device__ __forceinline__ float sigmf(float v) {
    return __fdividef(1.f, 1.f + __expf(-v));
}
__device__ __forceinline__ float tanhf_fast(float v) {
    return 1.f - __fdividef(2.f, 1.f + __expf(2.f * v));
}
__device__ __forceinline__ void lstm_cell(float gi, float gf, float gg, float go,
                                          float& c, float& h) {
    float iv = sigmf(gi);
    float fv = sigmf(gf);
    float gv = tanhf_fast(gg);
    float ov = sigmf(go);
    c = fv * c + iv * gv;
    h = ov * tanhf_fast(c);
}

__global__ __launch_bounds__(32) void k2_rnn(
    const float* __restrict__ Whh, const float* __restrict__ wfc,
    const float* __restrict__ bfc, float* __restrict__ out)
{
    __shared__ u64 hs[CH * 4];   // hs[k*4 + b] = {h_b[k], h_b[k]}

    const int j  = threadIdx.x;
    const int b0 = blockIdx.x * 4;

    // Register-resident recurrent weights, gate-paired
    const float* w_i = Whh + (0 * CH + j) * CH;
    const float* w_f = Whh + (1 * CH + j) * CH;
    const float* w_g = Whh + (2 * CH + j) * CH;
    const float* w_o = Whh + (3 * CH + j) * CH;
    u64 wr0[CH], wr1[CH];
    #pragma unroll
    for (int k = 0; k < CH; k++) {
        wr0[k] = pack2(w_i[k], w_f[k]);
        wr1[k] = pack2(w_g[k], w_o[k]);
    }

    // init h/c and shared h
    float c[4] = {0.f, 0.f, 0.f, 0.f};
    float h[4] = {0.f, 0.f, 0.f, 0.f};
    u64 z = pack2(0.f, 0.f);
    hs[j * 4 + 0] = z; hs[j * 4 + 1] = z; hs[j * 4 + 2] = z; hs[j * 4 + 3] = z;
    const float wfcv = wfc[j];
    __syncwarp();

    // xg pointers: element (t, b0+bi, pg, j)
    const u64* xbase = g_xg + (size_t)b0 * 64 + j;
    const size_t TSTRIDE = (size_t)CB * 64;

    // prefetch t=0
    u64 xc[4][2];
    #pragma unroll
    for (int bi = 0; bi < 4; bi++) {
        xc[bi][0] = __ldg(xbase + bi * 64);
        xc[bi][1] = __ldg(xbase + bi * 64 + 32);
    }
    const u64* xnext = xbase + TSTRIDE;

    for (int t = 0; t < CT; t++) {
        // prefetch next timestep (t=CT reads the padded extra slab, discarded)
        u64 xn[4][2];
        #pragma unroll
        for (int bi = 0; bi < 4; bi++) {
            xn[bi][0] = __ldg(xnext + bi * 64);
            xn[bi][1] = __ldg(xnext + bi * 64 + 32);
        }
        xnext += TSTRIDE;

        u64 acc[4][2];
        #pragma unroll
        for (int bi = 0; bi < 4; bi++) {
            acc[bi][0] = xc[bi][0];
            acc[bi][1] = xc[bi][1];
        }

        #pragma unroll
        for (int k = 0; k < CH; k++) {
            const ulonglong2 ha = *(const ulonglong2*)&hs[k * 4];      // b0,b1 dup
            const ulonglong2 hb = *(const ulonglong2*)&hs[k * 4 + 2];  // b2,b3 dup
            acc[0][0] = ffma2(ha.x, wr0[k], acc[0][0]);
            acc[0][1] = ffma2(ha.x, wr1[k], acc[0][1]);
            acc[1][0] = ffma2(ha.y, wr0[k], acc[1][0]);
            acc[1][1] = ffma2(ha.y, wr1[k], acc[1][1]);
            acc[2][0] = ffma2(hb.x, wr0[k], acc[2][0]);
            acc[2][1] = ffma2(hb.x, wr1[k], acc[2][1]);
            acc[3][0] = ffma2(hb.y, wr0[k], acc[3][0]);
            acc[3][1] = ffma2(hb.y, wr1[k], acc[3][1]);
        }
        __syncwarp();   // all lanes done reading hs(t)

        #pragma unroll
        for (int bi = 0; bi < 4; bi++) {
            float2 p0 = unpack2(acc[bi][0]);  // {i_pre, f_pre}
            float2 p1 = unpack2(acc[bi][1]);  // {g_pre, o_pre}
            lstm_cell(p0.x, p0.y, p1.x, p1.y, c[bi], h[bi]);
        }
        // publish h(t+1), duplicated, lane j owns k = j
        {
            ulonglong2 va, vb;
            va.x = pack2(h[0], h[0]);  va.y = pack2(h[1], h[1]);
            vb.x = pack2(h[2], h[2]);  vb.y = pack2(h[3], h[3]);
            *(ulonglong2*)&hs[j * 4]     = va;
            *(ulonglong2*)&hs[j * 4 + 2] = vb;
        }
        __syncwarp();   // hs(t+1) visible before next k-loop

        #pragma unroll
        for (int bi = 0; bi < 4; bi++) {
            xc[bi][0] = xn[bi][0];
            xc[bi][1] = xn[bi][1];
        }
    }

    // Fused fc: out[b] = sum_j h[b][j] * W_fc[0][j] + b_fc
    #pragma unroll
    for (int bi = 0; bi < 4; bi++) {
        float v = h[bi] * wfcv;
        #pragma unroll
        for (int off = 16; off > 0; off >>= 1)
            v += __shfl_xor_sync(0xffffffffu, v, off);
        if (j == 0) out[b0 + bi] = v + bfc[0];
    }
}

// ---------------------------------------------------------------------------
extern "C" void kernel_launch(void* const* d_in, const int* in_sizes, int n_in,
                              void* d_out, int out_size)
{
    const float* x   = (const float*)d_in[0];
    const float* Wih = (const float*)d_in[1];
    const float* Whh = (const float*)d_in[2];
    const float* bih = (const float*)d_in[3];
    const float* bhh = (const float*)d_in[4];
    const float* Wfc = (const float*)d_in[5];
    const float* bfc = (const float*)d_in[6];
    float* out = (float*)d_out;

    const int smem1 = 64 * WTS2 * 8 + 64 * XTS * 4;  // 66560 + 33792 = 100352 B
    cudaFuncSetAttribute(k1_inproj, cudaFuncAttributeMaxDynamicSharedMemorySize, smem1);

    dim3 g1(CB / 128, CT);
    k1_inproj<<<g1, 256, smem1>>>(x, Wih, bih, bhh);
    k2_rnn<<<CB / 4, 32>>>(Whh, Wfc, bfc, out);
}

// round 4
// speedup vs baseline: 1.2221x; 1.2221x over previous
#include <cuda_runtime.h>

typedef unsigned long long u64;

#define CB  2048
#define CT  512
#define CI  64
#define CH  32
#define CG  128

// Scratch: g_xg[((t*CB + b)*32 + j)*2 + {0,1}] = {(xg_i,xg_f),(xg_g,xg_o)} for unit j.
// One extra timestep slab so K2's t+1 prefetch never reads OOB.
__device__ u64 g_xg[(size_t)(CT + 1) * CB * 64];

__device__ __forceinline__ u64 ffma2(u64 a, u64 b, u64 c) {
    u64 d;
    asm("fma.rn.f32x2 %0, %1, %2, %3;" : "=l"(d) : "l"(a), "l"(b), "l"(c));
    return d;
}
__device__ __forceinline__ u64 pack2(float lo, float hi) {
    u64 d;
    asm("mov.b64 %0, {%1, %2};" : "=l"(d) : "f"(lo), "f"(hi));
    return d;
}
__device__ __forceinline__ float2 unpack2(u64 v) {
    float2 r;
    asm("mov.b64 {%0, %1}, %2;" : "=f"(r.x), "=f"(r.y) : "l"(v));
    return r;
}

// ---------------------------------------------------------------------------
// K1: input projection GEMM. Block = 256 thr, tile 128 batch x 128 gates,
// K=64, and 8 timesteps per block (W_ih staged once, x re-staged per t).
// Thread: 2 j-cols x 4 gate-blocks x 4 batch-pairs (f32x2 over batch).
// ---------------------------------------------------------------------------
#define WTS2 130   // u64 stride for Wt2 rows
#define XTS  132   // float stride for xs rows
#define TPB  8     // timesteps per block

extern __shared__ char sm1[];

__global__ __launch_bounds__(256, 2) void k1_inproj(
    const float* __restrict__ x, const float* __restrict__ Wih,
    const float* __restrict__ bih, const float* __restrict__ bhh)
{
    u64*   Wt2 = (u64*)sm1;                       // Wt2[k*WTS2 + g] = {w,w}
    float* xs  = (float*)(sm1 + 64 * WTS2 * 8);   // xs[k*XTS + r]
    const int tid = threadIdx.x;
    const int t0  = blockIdx.y * TPB;
    const int bt  = blockIdx.x * 128;

    // Stage W_ih duplicated (once per block)
    #pragma unroll
    for (int idx = tid; idx < CG * CI; idx += 256) {
        int g = idx >> 6, k = idx & 63;
        float w = Wih[idx];
        Wt2[k * WTS2 + g] = pack2(w, w);
    }

    const int tx = tid & 15, ty = tid >> 4;
    const int jj0 = tx * 2, r0 = ty * 8;

    // Bias pairs, kept across timesteps
    u64 bd[2][4];
    #pragma unroll
    for (int q = 0; q < 2; q++)
        #pragma unroll
        for (int gb = 0; gb < 4; gb++) {
            int g = gb * 32 + jj0 + q;
            float bs = bih[g] + bhh[g];
            bd[q][gb] = pack2(bs, bs);
        }

    for (int tt = 0; tt < TPB; tt++) {
        const int t = t0 + tt;
        __syncthreads();   // previous iteration done with xs
        #pragma unroll
        for (int idx = tid; idx < 128 * CI; idx += 256) {
            int r = idx >> 6, k = idx & 63;
            xs[k * XTS + r] = x[((size_t)(bt + r) * CT + t) * CI + k];
        }
        __syncthreads();

        u64 acc[2][4][4];
        #pragma unroll
        for (int q = 0; q < 2; q++)
            #pragma unroll
            for (int gb = 0; gb < 4; gb++)
                #pragma unroll
                for (int p = 0; p < 4; p++) acc[q][gb][p] = bd[q][gb];

        #pragma unroll 4
        for (int k = 0; k < CI; k++) {
            const ulonglong2 xa = *(const ulonglong2*)&xs[k * XTS + r0];
            const ulonglong2 xb = *(const ulonglong2*)&xs[k * XTS + r0 + 4];
            u64 xp[4] = {xa.x, xa.y, xb.x, xb.y};
            const ulonglong2 w0 = *(const ulonglong2*)&Wt2[k * WTS2 +  0 + jj0];
            const ulonglong2 w1 = *(const ulonglong2*)&Wt2[k * WTS2 + 32 + jj0];
            const ulonglong2 w2 = *(const ulonglong2*)&Wt2[k * WTS2 + 64 + jj0];
            const ulonglong2 w3 = *(const ulonglong2*)&Wt2[k * WTS2 + 96 + jj0];
            #pragma unroll
            for (int p = 0; p < 4; p++) {
                acc[0][0][p] = ffma2(xp[p], w0.x, acc[0][0][p]);
                acc[0][1][p] = ffma2(xp[p], w1.x, acc[0][1][p]);
                acc[0][2][p] = ffma2(xp[p], w2.x, acc[0][2][p]);
                acc[0][3][p] = ffma2(xp[p], w3.x, acc[0][3][p]);
                acc[1][0][p] = ffma2(xp[p], w0.y, acc[1][0][p]);
                acc[1][1][p] = ffma2(xp[p], w1.y, acc[1][1][p]);
                acc[1][2][p] = ffma2(xp[p], w2.y, acc[1][2][p]);
                acc[1][3][p] = ffma2(xp[p], w3.y, acc[1][3][p]);
            }
        }

        // Store: g_xg[((t*CB+b)*32 + j)*2 + {0,1}] = {(i,f),(g,o)}
        #pragma unroll
        for (int p = 0; p < 4; p++) {
            const int be = bt + r0 + 2 * p;
            #pragma unroll
            for (int q = 0; q < 2; q++) {
                float2 g0 = unpack2(acc[q][0][p]);
                float2 g1 = unpack2(acc[q][1][p]);
                float2 g2 = unpack2(acc[q][2][p]);
                float2 g3 = unpack2(acc[q][3][p]);
                u64* dst = g_xg + ((size_t)t * CB + be) * 64 + (jj0 + q) * 2;
                ulonglong2 ve, vo;
                ve.x = pack2(g0.x, g1.x);  ve.y = pack2(g2.x, g3.x);
                vo.x = pack2(g0.y, g1.y);  vo.y = pack2(g2.y, g3.y);
                *(ulonglong2*)dst        = ve;   // even batch
                *(ulonglong2*)(dst + 64) = vo;   // odd batch
            }
        }
    }
}

// ---------------------------------------------------------------------------
// K2: recurrence. 2 warps/block, each warp owns 4 batches; lane j = unit j.
// Weights smem pre-paired: Wp[k*32+j] = {(wi,wf),(wg,wo)}  (1 LDS.128/k).
// h smem pre-duplicated: hs[w][k][bi] = {h_bi[k], h_bi[k]}  (2 bc LDS.128/k).
// Inner loop per k: 3 LDS.128 + 8 FFMA2, zero packs. fc fused.
// ---------------------------------------------------------------------------
__device__ __forceinline__ float sigmf(float v) {
    return __fdividef(1.f, 1.f + __expf(-v));
}
__device__ __forceinline__ float tanhf_fast(float v) {
    return 1.f - __fdividef(2.f, 1.f + __expf(2.f * v));
}
__device__ __forceinline__ void lstm_cell(float gi, float gf, float gg, float go,
                                          float& c, float& h) {
    float iv = sigmf(gi);
    float fv = sigmf(gf);
    float gv = tanhf_fast(gg);
    float ov = sigmf(go);
    c = fv * c + iv * gv;
    h = ov * tanhf_fast(c);
}

#define K2W 2   // warps per block

__global__ __launch_bounds__(32 * K2W) void k2_rnn(
    const float* __restrict__ Whh, const float* __restrict__ wfc,
    const float* __restrict__ bfc, float* __restrict__ out)
{
    __shared__ ulonglong2 Wp[CH * CH];      // 16 KB, shared by both warps
    __shared__ u64 hs[K2W][CH][4];          // dup'd h per warp

    const int tid = threadIdx.x;
    const int j   = tid & 31;
    const int w   = tid >> 5;
    const int b0  = (blockIdx.x * K2W + w) * 4;

    // Stage paired weights: Wp[k*32+jj] = {(wi,wf),(wg,wo)} for unit jj
    for (int idx = tid; idx < CH * CH; idx += 32 * K2W) {
        int kk = idx >> 5, jj = idx & 31;
        ulonglong2 v;
        v.x = pack2(Whh[(0 * CH + jj) * CH + kk], Whh[(1 * CH + jj) * CH + kk]);
        v.y = pack2(Whh[(2 * CH + jj) * CH + kk], Whh[(3 * CH + jj) * CH + kk]);
        Wp[idx] = v;
    }
    {
        u64 z = pack2(0.f, 0.f);
        hs[w][j][0] = z; hs[w][j][1] = z; hs[w][j][2] = z; hs[w][j][3] = z;
    }
    float c[4] = {0.f, 0.f, 0.f, 0.f};
    float h[4] = {0.f, 0.f, 0.f, 0.f};
    const float wfcv = wfc[j];
    __syncthreads();

    // xg pointers: ((t*CB + b0+bi)*32 + j)*2 u64
    const u64* xptr = g_xg + ((size_t)b0) * 64 + j * 2;
    const size_t TSTRIDE = (size_t)CB * 64;

    ulonglong2 xc[4];
    #pragma unroll
    for (int bi = 0; bi < 4; bi++)
        xc[bi] = *(const ulonglong2*)(xptr + bi * 64);
    xptr += TSTRIDE;

    for (int t = 0; t < CT; t++) {
        ulonglong2 xn[4];
        #pragma unroll
        for (int bi = 0; bi < 4; bi++)
            xn[bi] = *(const ulonglong2*)(xptr + bi * 64);
        xptr += TSTRIDE;

        u64 acc[4][2];
        #pragma unroll
        for (int bi = 0; bi < 4; bi++) {
            acc[bi][0] = xc[bi].x;   // {i,f}
            acc[bi][1] = xc[bi].y;   // {g,o}
        }

        #pragma unroll
        for (int k = 0; k < CH; k++) {
            const ulonglong2 wv = Wp[k * 32 + j];                    // lane-distinct
            const ulonglong2 hA = *(const ulonglong2*)&hs[w][k][0];  // {<h0,h0>,<h1,h1>} bc
            const ulonglong2 hB = *(const ulonglong2*)&hs[w][k][2];  // {<h2,h2>,<h3,h3>} bc
            acc[0][0] = ffma2(hA.x, wv.x, acc[0][0]);
            acc[0][1] = ffma2(hA.x, wv.y, acc[0][1]);
            acc[1][0] = ffma2(hA.y, wv.x, acc[1][0]);
            acc[1][1] = ffma2(hA.y, wv.y, acc[1][1]);
            acc[2][0] = ffma2(hB.x, wv.x, acc[2][0]);
            acc[2][1] = ffma2(hB.x, wv.y, acc[2][1]);
            acc[3][0] = ffma2(hB.y, wv.x, acc[3][0]);
            acc[3][1] = ffma2(hB.y, wv.y, acc[3][1]);
        }
        __syncwarp();   // all lanes done reading hs(t)

        #pragma unroll
        for (int bi = 0; bi < 4; bi++) {
            float2 p0 = unpack2(acc[bi][0]);  // {i_pre, f_pre}
            float2 p1 = unpack2(acc[bi][1]);  // {g_pre, o_pre}
            lstm_cell(p0.x, p0.y, p1.x, p1.y, c[bi], h[bi]);
        }
        {
            ulonglong2 va, vb;
            va.x = pack2(h[0], h[0]);  va.y = pack2(h[1], h[1]);
            vb.x = pack2(h[2], h[2]);  vb.y = pack2(h[3], h[3]);
            *(ulonglong2*)&hs[w][j][0] = va;
            *(ulonglong2*)&hs[w][j][2] = vb;
        }
        __syncwarp();   // hs(t+1) visible

        #pragma unroll
        for (int bi = 0; bi < 4; bi++) xc[bi] = xn[bi];
    }

    // Fused fc: out[b] = sum_j h[b][j] * W_fc[0][j] + b_fc
    #pragma unroll
    for (int bi = 0; bi < 4; bi++) {
        float v = h[bi] * wfcv;
        #pragma unroll
        for (int off = 16; off > 0; off >>= 1)
            v += __shfl_xor_sync(0xffffffffu, v, off);
        if (j == 0) out[b0 + bi] = v + bfc[0];
    }
}

// ---------------------------------------------------------------------------
extern "C" void kernel_launch(void* const* d_in, const int* in_sizes, int n_in,
                              void* d_out, int out_size)
{
    const float* x   = (const float*)d_in[0];
    const float* Wih = (const float*)d_in[1];
    const float* Whh = (const float*)d_in[2];
    const float* bih = (const float*)d_in[3];
    const float* bhh = (const float*)d_in[4];
    const float* Wfc = (const float*)d_in[5];
    const float* bfc = (const float*)d_in[6];
    float* out = (float*)d_out;

    const int smem1 = 64 * WTS2 * 8 + 64 * XTS * 4;  // 100,352 B
    cudaFuncSetAttribute(k1_inproj, cudaFuncAttributeMaxDynamicSharedMemorySize, smem1);

    dim3 g1(CB / 128, CT / TPB);
    k1_inproj<<<g1, 256, smem1>>>(x, Wih, bih, bhh);
    k2_rnn<<<CB / (4 * K2W), 32 * K2W>>>(Whh, Wfc, bfc, out);
}